// round 2
// baseline (speedup 1.0000x reference)
#include <cuda_runtime.h>

#define NN 8192
#define CC 32

// ---------------- scratch (no allocations allowed; __device__ globals) -------
__device__ float g_xm[NN * 64];     // x_mean concat [q][64]
__device__ float g_xv[NN * 96];     // x_var  concat [q][96]
__device__ float g_nq_m[NN];        // |x_mean[q]|^2
__device__ float g_nq_v[NN];        // |x_var[q]|^2
__device__ float g_nX_m[NN];        // |X_mean[i]|^2
__device__ float g_nX_v[NN];        // |X_var[i]|^2
__device__ float g_Lam_m[NN * CC];  // kXXmean_inv @ Z_mean
__device__ float g_Lam_v[NN * CC];  // kXXvar_inv  @ Z_var
__device__ float g_zm[NN * CC];     // z_mean
__device__ float g_zv[NN * CC];     // z_var

__device__ __forceinline__ float warp_sum(float v) {
#pragma unroll
    for (int o = 16; o; o >>= 1) v += __shfl_xor_sync(0xffffffffu, v, o);
    return v;
}

// ---------------- prep: concats + row norms ---------------------------------
// blockDim = (32, 8); one warp per row q; lane = feature c.
__global__ void prep_kernel(const float* __restrict__ x_mu,
                            const float* __restrict__ y_eta,
                            const float* __restrict__ y_mean,
                            const float* __restrict__ y_var,
                            const float* __restrict__ X_mean,
                            const float* __restrict__ X_var) {
    const int q = blockIdx.x * blockDim.y + threadIdx.y;
    const int c = threadIdx.x;

    const float xm = x_mu[q * 32 + c];
    const float s  = y_mean[q * 32 + c] + y_var[q * 32 + c];
    const float e  = 0.01f * y_eta[(NN - 1 - q) * 32 + c];  // row flip!

    g_xm[q * 64 + c]      = xm;
    g_xm[q * 64 + 32 + c] = s;
    g_xv[q * 96 + c]      = xm;
    g_xv[q * 96 + 32 + c] = e;
    g_xv[q * 96 + 64 + c] = s;

    const float nm = warp_sum(xm * xm + s * s);
    const float ne = warp_sum(e * e);
    if (c == 0) { g_nq_m[q] = nm; g_nq_v[q] = nm + ne; }

    const float a0 = X_mean[q * 64 + c];
    const float a1 = X_mean[q * 64 + 32 + c];
    const float sm = warp_sum(a0 * a0 + a1 * a1);
    const float u0 = X_var[q * 96 + c];
    const float u1 = X_var[q * 96 + 32 + c];
    const float u2 = X_var[q * 96 + 64 + c];
    const float sv = warp_sum(u0 * u0 + u1 * u1 + u2 * u2);
    if (c == 0) { g_nX_m[q] = sm; g_nX_v[q] = sv; }
}

// ---------------- Lambda = kXX_inv @ Z  ([N,N]@[N,32]) ----------------------
// BM=128 rows per CTA, BK=32, 256 threads, 4x4 microtile per thread.
// A tile stored transposed in SMEM (As[kk][row], stride 132) for LDS.128 feeds.
__global__ void lambda_kernel(const float* __restrict__ kXm,
                              const float* __restrict__ kXv,
                              const float* __restrict__ Zm,
                              const float* __restrict__ Zv) {
    const float* __restrict__ A;
    const float* __restrict__ B;
    float* __restrict__ O;
    if (blockIdx.y == 0) { A = kXm; B = Zm; O = g_Lam_m; }
    else                 { A = kXv; B = Zv; O = g_Lam_v; }

    __shared__ float As[32][132];  // [kk][row], pad keeps LDS.128 conflict-free
    __shared__ float Bs[32][32];   // [kk][col]

    const int tid  = threadIdx.x;      // 0..255
    const int row0 = blockIdx.x * 128;
    const int cx   = tid & 7;          // col group: c0 = cx*4
    const int ry   = tid >> 3;         // row group: r0 = ry*4

    float acc[4][4] = {};

    for (int k0 = 0; k0 < NN; k0 += 32) {
        // load A tile (128x32) and transpose into SMEM
#pragma unroll
        for (int it = 0; it < 4; it++) {
            const int lin4 = it * 256 + tid;   // 1024 float4 total
            const int r    = lin4 >> 3;        // 0..127
            const int kq   = lin4 & 7;         // k = kq*4
            const float4 v = *(const float4*)&A[(row0 + r) * NN + k0 + kq * 4];
            As[kq * 4 + 0][r] = v.x;
            As[kq * 4 + 1][r] = v.y;
            As[kq * 4 + 2][r] = v.z;
            As[kq * 4 + 3][r] = v.w;
        }
        {
            const int kk = tid >> 3, cq = tid & 7;
            *(float4*)&Bs[kk][cq * 4] =
                *(const float4*)&B[(k0 + kk) * 32 + cq * 4];
        }
        __syncthreads();

#pragma unroll
        for (int kk = 0; kk < 32; kk++) {
            const float4 a4 = *(const float4*)&As[kk][ry * 4];
            const float4 b4 = *(const float4*)&Bs[kk][cx * 4];
            const float a[4] = {a4.x, a4.y, a4.z, a4.w};
            const float b[4] = {b4.x, b4.y, b4.z, b4.w};
#pragma unroll
            for (int m = 0; m < 4; m++)
#pragma unroll
                for (int n = 0; n < 4; n++) acc[m][n] += a[m] * b[n];
        }
        __syncthreads();
    }

#pragma unroll
    for (int m = 0; m < 4; m++) {
        float4 v = make_float4(acc[m][0], acc[m][1], acc[m][2], acc[m][3]);
        *(float4*)&O[(row0 + ry * 4 + m) * 32 + cx * 4] = v;
    }
}

// ---------------- fused RBF: z = exp(-d2/128)^T @ Lambda --------------------
// grid (128, 2): x = 64-query block, y = pass (0: mean D=64, 1: var D=96).
// Per tile of 64 i's: S-phase (4x4 microtile GEMM + exp into SMEM K),
// then Z-phase accumulates z[q][c] in registers. K never touches GMEM.
#define RBF_SMEM_FLOATS (96 * 64 * 2 + 64 * 68 + 64 * 32 + 128)
#define RBF_SMEM_BYTES  (RBF_SMEM_FLOATS * 4)

__global__ void rbf_kernel(const float* __restrict__ X_mean,
                           const float* __restrict__ X_var) {
    const int pass = blockIdx.y;
    const float* __restrict__ X   = pass ? X_var   : X_mean;
    const float* __restrict__ xq  = pass ? g_xv    : g_xm;
    const float* __restrict__ nX  = pass ? g_nX_v  : g_nX_m;
    const float* __restrict__ nq  = pass ? g_nq_v  : g_nq_m;
    const float* __restrict__ Lam = pass ? g_Lam_v : g_Lam_m;
    float* __restrict__ zout      = pass ? g_zv    : g_zm;
    const int D = pass ? 96 : 64;

    extern __shared__ float smem[];
    float* xs  = smem;             // [96][64]  query tile, d-major
    float* Xs  = xs + 96 * 64;     // [96][64]  X tile, d-major
    float* Ks  = Xs + 96 * 64;     // [64][68]  K tile [ii][qq], padded
    float* Ls  = Ks + 64 * 68;     // [64][32]  Lambda tile
    float* nqs = Ls + 64 * 32;     // [64]
    float* nXs = nqs + 64;         // [64]

    const int tid = threadIdx.x;   // 256
    const int q0  = blockIdx.x * 64;
    const int nf4 = 64 * (D / 4);

    // load query tile transposed (once)
    for (int lin4 = tid; lin4 < nf4; lin4 += 256) {
        const int qq = lin4 / (D / 4);
        const int dq = lin4 % (D / 4);
        const float4 v = *(const float4*)&xq[(q0 + qq) * D + dq * 4];
        xs[(dq * 4 + 0) * 64 + qq] = v.x;
        xs[(dq * 4 + 1) * 64 + qq] = v.y;
        xs[(dq * 4 + 2) * 64 + qq] = v.z;
        xs[(dq * 4 + 3) * 64 + qq] = v.w;
    }
    if (tid < 64) nqs[tid] = nq[q0 + tid];

    const int qx = tid & 15;       // S-phase: q microtile group
    const int iy = tid >> 4;       // S-phase: i microtile group
    const int zq = tid & 63;       // Z-phase: q
    const int zc = (tid >> 6) * 8; // Z-phase: c base (8 cols per thread)

    float acc[8] = {0, 0, 0, 0, 0, 0, 0, 0};

    for (int i0 = 0; i0 < NN; i0 += 64) {
        __syncthreads();  // previous Z-phase done reading tiles
        for (int lin4 = tid; lin4 < nf4; lin4 += 256) {
            const int ii = lin4 / (D / 4);
            const int dq = lin4 % (D / 4);
            const float4 v = *(const float4*)&X[(i0 + ii) * D + dq * 4];
            Xs[(dq * 4 + 0) * 64 + ii] = v.x;
            Xs[(dq * 4 + 1) * 64 + ii] = v.y;
            Xs[(dq * 4 + 2) * 64 + ii] = v.z;
            Xs[(dq * 4 + 3) * 64 + ii] = v.w;
        }
        for (int lin4 = tid; lin4 < 512; lin4 += 256) {
            const int ii = lin4 >> 3;
            const int cq = lin4 & 7;
            *(float4*)&Ls[ii * 32 + cq * 4] =
                *(const float4*)&Lam[(i0 + ii) * 32 + cq * 4];
        }
        if (tid < 64) nXs[tid] = nX[i0 + tid];
        __syncthreads();

        // ---- S-phase: S[i][q] = X[i] . x[q], then K = exp(-max(d2,0)/128)
        float s[4][4] = {};
#pragma unroll 8
        for (int d = 0; d < D; d++) {
            const float4 a4 = *(const float4*)&Xs[d * 64 + iy * 4];
            const float4 b4 = *(const float4*)&xs[d * 64 + qx * 4];
            const float a[4] = {a4.x, a4.y, a4.z, a4.w};
            const float b[4] = {b4.x, b4.y, b4.z, b4.w};
#pragma unroll
            for (int m = 0; m < 4; m++)
#pragma unroll
                for (int n = 0; n < 4; n++) s[m][n] += a[m] * b[n];
        }
#pragma unroll
        for (int m = 0; m < 4; m++) {
            const float na = nXs[iy * 4 + m];
#pragma unroll
            for (int n = 0; n < 4; n++) {
                float d2 = na + nqs[qx * 4 + n] - 2.0f * s[m][n];
                d2 = fmaxf(d2, 0.0f);
                Ks[(iy * 4 + m) * 68 + qx * 4 + n] = __expf(d2 * -0.0078125f);
            }
        }
        __syncthreads();

        // ---- Z-phase: z[q][c] += sum_ii K[ii][q] * Lam[ii][c]
#pragma unroll 4
        for (int ii = 0; ii < 64; ii++) {
            const float  k  = Ks[ii * 68 + zq];
            const float4 l0 = *(const float4*)&Ls[ii * 32 + zc];
            const float4 l1 = *(const float4*)&Ls[ii * 32 + zc + 4];
            acc[0] += k * l0.x; acc[1] += k * l0.y;
            acc[2] += k * l0.z; acc[3] += k * l0.w;
            acc[4] += k * l1.x; acc[5] += k * l1.y;
            acc[6] += k * l1.z; acc[7] += k * l1.w;
        }
    }

    *(float4*)&zout[(q0 + zq) * 32 + zc] =
        make_float4(acc[0], acc[1], acc[2], acc[3]);
    *(float4*)&zout[(q0 + zq) * 32 + zc + 4] =
        make_float4(acc[4], acc[5], acc[6], acc[7]);
}

// ---------------- final combine ---------------------------------------------
__global__ void combine_kernel(const float* __restrict__ y_mean,
                               const float* __restrict__ y_var,
                               float* __restrict__ out) {
    const int i = blockIdx.x * 256 + threadIdx.x;
    out[i] = (y_mean[i] + g_zm[i]) + (y_var[i] + g_zv[i]);
}

// ---------------- launch -----------------------------------------------------
extern "C" void kernel_launch(void* const* d_in, const int* in_sizes, int n_in,
                              void* d_out, int out_size) {
    (void)in_sizes; (void)n_in; (void)out_size;
    const float* x_mu   = (const float*)d_in[0];
    const float* y_eta  = (const float*)d_in[1];
    const float* y_mean = (const float*)d_in[2];
    const float* y_var  = (const float*)d_in[3];
    const float* X_mean = (const float*)d_in[4];
    const float* X_var  = (const float*)d_in[5];
    const float* Z_mean = (const float*)d_in[6];
    const float* Z_var  = (const float*)d_in[7];
    const float* kXm    = (const float*)d_in[8];
    const float* kXv    = (const float*)d_in[9];
    float* out = (float*)d_out;

    cudaFuncSetAttribute(rbf_kernel,
                         cudaFuncAttributeMaxDynamicSharedMemorySize,
                         RBF_SMEM_BYTES);

    prep_kernel<<<NN / 8, dim3(32, 8)>>>(x_mu, y_eta, y_mean, y_var,
                                         X_mean, X_var);
    lambda_kernel<<<dim3(64, 2), 256>>>(kXm, kXv, Z_mean, Z_var);
    rbf_kernel<<<dim3(128, 2), 256, RBF_SMEM_BYTES>>>(X_mean, X_var);
    combine_kernel<<<(NN * CC) / 256, 256>>>(y_mean, y_var, out);
}

// round 4
// speedup vs baseline: 2.1501x; 2.1501x over previous
#include <cuda_runtime.h>
#include <cuda_bf16.h>

#define NN 8192
#define CC 32

// ---------------- scratch (__device__ globals; no allocations) ---------------
__device__ float g_xm[NN * 64];     // x_mean concat [q][64]
__device__ float g_xv[NN * 96];     // x_var  concat [q][96]
__device__ float g_nq_m[NN];
__device__ float g_nq_v[NN];
__device__ float g_nX_m[NN];
__device__ float g_nX_v[NN];
__device__ float g_Lam_m[NN * CC];
__device__ float g_Lam_v[NN * CC];
__device__ float g_zm[NN * CC];
__device__ float g_zv[NN * CC];

// ---------------- helpers -----------------------------------------------------
__device__ __forceinline__ unsigned smem_u32(const void* ptr) {
    unsigned a;
    asm("{ .reg .u64 t; cvta.to.shared.u64 t, %1; cvt.u32.u64 %0, t; }"
        : "=r"(a) : "l"(ptr));
    return a;
}

__device__ __forceinline__ void ldsm4(unsigned& r0, unsigned& r1,
                                      unsigned& r2, unsigned& r3, unsigned a) {
    asm volatile("ldmatrix.sync.aligned.m8n8.x4.shared.b16 {%0,%1,%2,%3}, [%4];"
                 : "=r"(r0), "=r"(r1), "=r"(r2), "=r"(r3) : "r"(a));
}

// mma.sync m16n8k16 row.col bf16 -> f32 (plain sm_80+ PTX; HMMA on sm_103)
__device__ __forceinline__ void mma16816(float* c, unsigned a0, unsigned a1,
                                         unsigned a2, unsigned a3,
                                         unsigned b0, unsigned b1) {
    asm volatile(
        "mma.sync.aligned.m16n8k16.row.col.f32.bf16.bf16.f32 "
        "{%0,%1,%2,%3}, {%4,%5,%6,%7}, {%8,%9}, {%0,%1,%2,%3};"
        : "+f"(c[0]), "+f"(c[1]), "+f"(c[2]), "+f"(c[3])
        : "r"(a0), "r"(a1), "r"(a2), "r"(a3), "r"(b0), "r"(b1));
}

// split-bf16: x = hi + lo (+ O(2^-18 |x|))
__device__ __forceinline__ void split_pair(float a, float b,
                                           unsigned& hi, unsigned& lo) {
    __nv_bfloat16 ah = __float2bfloat16(a);
    __nv_bfloat16 bh = __float2bfloat16(b);
    float ar = a - __bfloat162float(ah);
    float br = b - __bfloat162float(bh);
    __nv_bfloat162 h; h.x = ah; h.y = bh;
    __nv_bfloat162 l; l.x = __float2bfloat16(ar); l.y = __float2bfloat16(br);
    hi = *reinterpret_cast<unsigned*>(&h);
    lo = *reinterpret_cast<unsigned*>(&l);
}
__device__ __forceinline__ void split1(float a, __nv_bfloat16& h, __nv_bfloat16& l) {
    h = __float2bfloat16(a);
    l = __float2bfloat16(a - __bfloat162float(h));
}

__device__ __forceinline__ float warp_sum(float v) {
#pragma unroll
    for (int o = 16; o; o >>= 1) v += __shfl_xor_sync(0xffffffffu, v, o);
    return v;
}

// ---------------- prep: concats + row norms (validated round 1) --------------
__global__ void prep_kernel(const float* __restrict__ x_mu,
                            const float* __restrict__ y_eta,
                            const float* __restrict__ y_mean,
                            const float* __restrict__ y_var,
                            const float* __restrict__ X_mean,
                            const float* __restrict__ X_var) {
    const int q = blockIdx.x * blockDim.y + threadIdx.y;
    const int c = threadIdx.x;

    const float xm = x_mu[q * 32 + c];
    const float s  = y_mean[q * 32 + c] + y_var[q * 32 + c];
    const float e  = 0.01f * y_eta[(NN - 1 - q) * 32 + c];  // row flip

    g_xm[q * 64 + c]      = xm;
    g_xm[q * 64 + 32 + c] = s;
    g_xv[q * 96 + c]      = xm;
    g_xv[q * 96 + 32 + c] = e;
    g_xv[q * 96 + 64 + c] = s;

    const float nm = warp_sum(xm * xm + s * s);
    const float ne = warp_sum(e * e);
    if (c == 0) { g_nq_m[q] = nm; g_nq_v[q] = nm + ne; }

    const float a0 = X_mean[q * 64 + c];
    const float a1 = X_mean[q * 64 + 32 + c];
    const float sm = warp_sum(a0 * a0 + a1 * a1);
    const float u0 = X_var[q * 96 + c];
    const float u1 = X_var[q * 96 + 32 + c];
    const float u2 = X_var[q * 96 + 64 + c];
    const float sv = warp_sum(u0 * u0 + u1 * u1 + u2 * u2);
    if (c == 0) { g_nX_m[q] = sm; g_nX_v[q] = sv; }
}

// ---------------- Lambda = kXX_inv @ Z via mma.sync bf16 split ---------------
// CTA: 128 rows, 256 threads (8 warps, m16 each, full n=32).
// SMEM (padded rows, odd multiples of 16B -> conflict-free ldmatrix):
//   AH [128][72] @0 (18432)  AL @18432
//   ZTH [32][72] @36864 (4608)  ZTL @41472   -> 46080 total (static)
__global__ __launch_bounds__(256, 1)
void lambda_mma_kernel(const float* __restrict__ kXm,
                       const float* __restrict__ kXv,
                       const float* __restrict__ Zm,
                       const float* __restrict__ Zv) {
    const float* __restrict__ A;
    const float* __restrict__ B;
    float* __restrict__ O;
    if (blockIdx.y == 0) { A = kXm; B = Zm; O = g_Lam_m; }
    else                 { A = kXv; B = Zv; O = g_Lam_v; }

    __shared__ __align__(16) char smem[46080];
    const unsigned sb = smem_u32(smem);
    const int tid = threadIdx.x, wid = tid >> 5, lane = tid & 31;
    const int row0 = blockIdx.x * 128;

    const unsigned AH = 0, AL = 18432, ZTH = 36864, ZTL = 41472;
    float acc[4][4] = {};

    for (int c = 0; c < 128; c++) {
        __syncthreads();
        // A tile [128][64] fp32 -> hi/lo bf16, row stride 144B
        for (int idx = tid; idx < 128 * 16; idx += 256) {
            const int r = idx >> 4, d = (idx & 15) * 4;
            const float4 v =
                *(const float4*)&A[(size_t)(row0 + r) * NN + c * 64 + d];
            unsigned h0, l0, h1, l1;
            split_pair(v.x, v.y, h0, l0);
            split_pair(v.z, v.w, h1, l1);
            const unsigned off = r * 144 + d * 2;
            *(uint2*)(smem + AH + off) = make_uint2(h0, h1);
            *(uint2*)(smem + AL + off) = make_uint2(l0, l1);
        }
        // Z^T tile [32 n][64 k]
        for (int e = tid; e < 2048; e += 256) {
            const int kk = e >> 5, cc2 = e & 31;
            const float v = B[(size_t)(c * 64 + kk) * 32 + cc2];
            __nv_bfloat16 h, l;
            split1(v, h, l);
            const unsigned off = cc2 * 144 + kk * 2;
            *(__nv_bfloat16*)(smem + ZTH + off) = h;
            *(__nv_bfloat16*)(smem + ZTL + off) = l;
        }
        __syncthreads();

        const int m0 = wid * 16;
#pragma unroll
        for (int sp = 0; sp < 3; sp++) {
            const unsigned ab = sb + (sp == 2 ? AL : AH);
            const unsigned bb = sb + (sp == 1 ? ZTL : ZTH);
#pragma unroll
            for (int ks = 0; ks < 4; ks++) {
                unsigned a0, a1, a2, a3;
                ldsm4(a0, a1, a2, a3,
                      ab + (m0 + (lane & 15)) * 144 +
                          (ks * 16 + (lane >> 4) * 8) * 2);
                const unsigned baddr =
                    bb + ((lane & 7) + ((lane >> 4) << 3)) * 144 +
                    (ks * 16 + ((lane >> 3) & 1) * 8) * 2;
                unsigned b0, b1, b2, b3, b4, b5, b6, b7;
                ldsm4(b0, b1, b2, b3, baddr);
                ldsm4(b4, b5, b6, b7, baddr + 16 * 144);
                mma16816(acc[0], a0, a1, a2, a3, b0, b1);
                mma16816(acc[1], a0, a1, a2, a3, b2, b3);
                mma16816(acc[2], a0, a1, a2, a3, b4, b5);
                mma16816(acc[3], a0, a1, a2, a3, b6, b7);
            }
        }
    }

    const int r0 = row0 + wid * 16 + (lane >> 2), r1 = r0 + 8;
    const int cb = (lane & 3) * 2;
#pragma unroll
    for (int nf = 0; nf < 4; nf++) {
        *(float2*)&O[(size_t)r0 * 32 + nf * 8 + cb] =
            make_float2(acc[nf][0], acc[nf][1]);
        *(float2*)&O[(size_t)r1 * 32 + nf * 8 + cb] =
            make_float2(acc[nf][2], acc[nf][3]);
    }
}

// ---------------- fused RBF via mma.sync: S -> exp -> K -> z -----------------
// grid (64, 2): 128 queries/CTA, pass 0 (D=64) / 1 (D=96). 256 threads.
// SMEM offsets (bytes); all row strides are odd multiples of 16B:
//   XQH@0       [128][104] 26624    XQL@26624
//   XH @53248   [128][104] 26624    XL @79872
//   KH @106496  [128][136] 34816    KL @141312
//   LTH@176128  [32][136]  8704     LTL@184832
//   NQS@193536 (512)  NXS@194048 (512)  -> 194560 total
#define RBF_SMEM_BYTES 194560

__global__ __launch_bounds__(256, 1)
void rbf_mma_kernel(const float* __restrict__ X_mean,
                    const float* __restrict__ X_var) {
    const int pass = blockIdx.y;
    const float* __restrict__ X   = pass ? X_var   : X_mean;
    const float* __restrict__ xq  = pass ? g_xv    : g_xm;
    const float* __restrict__ nX  = pass ? g_nX_v  : g_nX_m;
    const float* __restrict__ nq  = pass ? g_nq_v  : g_nq_m;
    const float* __restrict__ Lm  = pass ? g_Lam_v : g_Lam_m;
    float* __restrict__ zout      = pass ? g_zv    : g_zm;
    const int D  = pass ? 96 : 64;
    const int dv = D / 4;
    const int dk = D / 16;

    extern __shared__ __align__(16) char smem[];
    const unsigned sb = smem_u32(smem);
    const unsigned XQH = 0, XQL = 26624, XH = 53248, XL = 79872;
    const unsigned KH = 106496, KL = 141312, LTH = 176128, LTL = 184832;
    float* nqs = (float*)(smem + 193536);
    float* nXs = (float*)(smem + 194048);

    const int tid = threadIdx.x, wid = tid >> 5, lane = tid & 31;
    const int q0 = blockIdx.x * 128;
    const int qr = lane >> 2, cc2 = (lane & 3) * 2;

    // persistent query tiles (hi/lo), row stride 208B
    for (int idx = tid; idx < 128 * dv; idx += 256) {
        const int r = idx / dv, d = (idx % dv) * 4;
        const float4 v = *(const float4*)&xq[(size_t)(q0 + r) * D + d];
        unsigned h0, l0, h1, l1;
        split_pair(v.x, v.y, h0, l0);
        split_pair(v.z, v.w, h1, l1);
        const unsigned off = r * 208 + d * 2;
        *(uint2*)(smem + XQH + off) = make_uint2(h0, h1);
        *(uint2*)(smem + XQL + off) = make_uint2(l0, l1);
    }
    if (tid < 128) nqs[tid] = nq[q0 + tid];

    const int mS = (wid & 3) * 32, nS = (wid >> 2) * 64;  // S-phase warp tile
    const int mZ = wid * 16;                              // Z-phase warp tile

    float zacc[4][4] = {};

    for (int it = 0; it < 64; it++) {
        const int i0 = it * 128;
        __syncthreads();  // prev Z-phase done with LT/K; loads may overwrite

        // X tile (hi/lo) + Lambda^T tile (hi/lo) + nXs
        for (int idx = tid; idx < 128 * dv; idx += 256) {
            const int r = idx / dv, d = (idx % dv) * 4;
            const float4 v = *(const float4*)&X[(size_t)(i0 + r) * D + d];
            unsigned h0, l0, h1, l1;
            split_pair(v.x, v.y, h0, l0);
            split_pair(v.z, v.w, h1, l1);
            const unsigned off = r * 208 + d * 2;
            *(uint2*)(smem + XH + off) = make_uint2(h0, h1);
            *(uint2*)(smem + XL + off) = make_uint2(l0, l1);
        }
        for (int e = tid; e < 4096; e += 256) {
            const int ii = e >> 5, cc = e & 31;
            const float v = Lm[(size_t)(i0 + ii) * 32 + cc];
            __nv_bfloat16 h, l;
            split1(v, h, l);
            const unsigned off = cc * 272 + ii * 2;
            *(__nv_bfloat16*)(smem + LTH + off) = h;
            *(__nv_bfloat16*)(smem + LTL + off) = l;
        }
        if (tid < 128) nXs[tid] = nX[i0 + tid];
        __syncthreads();

        // ---- S phase: S[mS..+32][nS..+64], 3-way split
        float sa[2][8][4];
#pragma unroll
        for (int mf = 0; mf < 2; mf++)
#pragma unroll
            for (int nf = 0; nf < 8; nf++)
#pragma unroll
                for (int j = 0; j < 4; j++) sa[mf][nf][j] = 0.0f;

#pragma unroll
        for (int sp = 0; sp < 3; sp++) {
            const unsigned ab = sb + (sp == 2 ? XQL : XQH);
            const unsigned bb = sb + (sp == 1 ? XL : XH);
            for (int ks = 0; ks < dk; ks++) {
                unsigned a[2][4];
#pragma unroll
                for (int mf = 0; mf < 2; mf++)
                    ldsm4(a[mf][0], a[mf][1], a[mf][2], a[mf][3],
                          ab + (mS + mf * 16 + (lane & 15)) * 208 +
                              (ks * 16 + (lane >> 4) * 8) * 2);
#pragma unroll
                for (int nb = 0; nb < 4; nb++) {
                    unsigned b0, b1, b2, b3;
                    ldsm4(b0, b1, b2, b3,
                          bb + (nS + nb * 16 + (lane & 7) + ((lane >> 4) << 3)) * 208 +
                              (ks * 16 + ((lane >> 3) & 1) * 8) * 2);
#pragma unroll
                    for (int mf = 0; mf < 2; mf++) {
                        mma16816(sa[mf][nb * 2],     a[mf][0], a[mf][1],
                                 a[mf][2], a[mf][3], b0, b1);
                        mma16816(sa[mf][nb * 2 + 1], a[mf][0], a[mf][1],
                                 a[mf][2], a[mf][3], b2, b3);
                    }
                }
            }
        }

        // ---- epilogue: K = exp(-max(d2,0)/128), split, store K tiles
#pragma unroll
        for (int mf = 0; mf < 2; mf++) {
            const int r0 = mS + mf * 16 + qr, r1 = r0 + 8;
            const float nq0 = nqs[r0], nq1 = nqs[r1];
#pragma unroll
            for (int nf = 0; nf < 8; nf++) {
                const int col = nS + nf * 8 + cc2;
                const float2 nx = *(const float2*)&nXs[col];
                const float* s = sa[mf][nf];
                const float k00 =
                    __expf(fmaxf(nq0 + nx.x - 2.0f * s[0], 0.0f) * -0.0078125f);
                const float k01 =
                    __expf(fmaxf(nq0 + nx.y - 2.0f * s[1], 0.0f) * -0.0078125f);
                const float k10 =
                    __expf(fmaxf(nq1 + nx.x - 2.0f * s[2], 0.0f) * -0.0078125f);
                const float k11 =
                    __expf(fmaxf(nq1 + nx.y - 2.0f * s[3], 0.0f) * -0.0078125f);
                unsigned h, l;
                split_pair(k00, k01, h, l);
                *(unsigned*)(smem + KH + r0 * 272 + col * 2) = h;
                *(unsigned*)(smem + KL + r0 * 272 + col * 2) = l;
                split_pair(k10, k11, h, l);
                *(unsigned*)(smem + KH + r1 * 272 + col * 2) = h;
                *(unsigned*)(smem + KL + r1 * 272 + col * 2) = l;
            }
        }
        __syncthreads();

        // ---- Z phase: z[mZ..+16][0..31] += K @ Lambda, 3-way split
#pragma unroll
        for (int sp = 0; sp < 3; sp++) {
            const unsigned ab = sb + (sp == 2 ? KL : KH);
            const unsigned bb = sb + (sp == 1 ? LTL : LTH);
#pragma unroll
            for (int ks = 0; ks < 8; ks++) {
                unsigned a0, a1, a2, a3;
                ldsm4(a0, a1, a2, a3,
                      ab + (mZ + (lane & 15)) * 272 +
                          (ks * 16 + (lane >> 4) * 8) * 2);
                const unsigned baddr =
                    bb + ((lane & 7) + ((lane >> 4) << 3)) * 272 +
                    (ks * 16 + ((lane >> 3) & 1) * 8) * 2;
                unsigned b0, b1, b2, b3, b4, b5, b6, b7;
                ldsm4(b0, b1, b2, b3, baddr);
                ldsm4(b4, b5, b6, b7, baddr + 16 * 272);
                mma16816(zacc[0], a0, a1, a2, a3, b0, b1);
                mma16816(zacc[1], a0, a1, a2, a3, b2, b3);
                mma16816(zacc[2], a0, a1, a2, a3, b4, b5);
                mma16816(zacc[3], a0, a1, a2, a3, b6, b7);
            }
        }
    }

    // write z
    const int r0 = q0 + mZ + qr, r1 = r0 + 8;
#pragma unroll
    for (int nf = 0; nf < 4; nf++) {
        *(float2*)&zout[(size_t)r0 * 32 + nf * 8 + cc2] =
            make_float2(zacc[nf][0], zacc[nf][1]);
        *(float2*)&zout[(size_t)r1 * 32 + nf * 8 + cc2] =
            make_float2(zacc[nf][2], zacc[nf][3]);
    }
}

// ---------------- final combine ----------------------------------------------
__global__ void combine_kernel(const float* __restrict__ y_mean,
                               const float* __restrict__ y_var,
                               float* __restrict__ out) {
    const int i = blockIdx.x * 256 + threadIdx.x;
    out[i] = (y_mean[i] + g_zm[i]) + (y_var[i] + g_zv[i]);
}

// ---------------- launch ------------------------------------------------------
extern "C" void kernel_launch(void* const* d_in, const int* in_sizes, int n_in,
                              void* d_out, int out_size) {
    (void)in_sizes; (void)n_in; (void)out_size;
    const float* x_mu   = (const float*)d_in[0];
    const float* y_eta  = (const float*)d_in[1];
    const float* y_mean = (const float*)d_in[2];
    const float* y_var  = (const float*)d_in[3];
    const float* X_mean = (const float*)d_in[4];
    const float* X_var  = (const float*)d_in[5];
    const float* Z_mean = (const float*)d_in[6];
    const float* Z_var  = (const float*)d_in[7];
    const float* kXm    = (const float*)d_in[8];
    const float* kXv    = (const float*)d_in[9];
    float* out = (float*)d_out;

    cudaFuncSetAttribute(rbf_mma_kernel,
                         cudaFuncAttributeMaxDynamicSharedMemorySize,
                         RBF_SMEM_BYTES);

    prep_kernel<<<NN / 8, dim3(32, 8)>>>(x_mu, y_eta, y_mean, y_var,
                                         X_mean, X_var);
    lambda_mma_kernel<<<dim3(64, 2), 256>>>(kXm, kXv, Z_mean, Z_var);
    rbf_mma_kernel<<<dim3(64, 2), 256, RBF_SMEM_BYTES>>>(X_mean, X_var);
    combine_kernel<<<(NN * CC) / 256, 256>>>(y_mean, y_var, out);
}